// round 2
// baseline (speedup 1.0000x reference)
#include <cuda_runtime.h>
#include <math.h>

// LSTMBackbone: 2-layer LSTM, S=256, B=256, I=256, H=512, done-mask reset.
// Persistent single-kernel design: 128 CTAs, custom grid barrier, 1 sync/step.
// Each CTA computes a 32x32 (batch x hidden) tile of cells, all 4 gates.

#define S_ 256
#define B_ 256
#define I_ 256
#define H_ 512
#define NBLK 128
#define NTHR 256
#define KC 32

// ---- persistent device state (allocation-free scratch) ----
__device__ float g_H0buf[2][B_ * H_];   // layer0 h, masked, parity ping-pong
__device__ float g_H1buf[2][B_ * H_];   // layer1 h, masked, parity ping-pong
__device__ float g_H0new[2][B_ * H_];   // layer0 h unmasked (feeds layer1), parity
__device__ float g_C0[B_ * H_];         // cell states (owner-thread access only)
__device__ float g_C1[B_ * H_];
__device__ unsigned g_bar_count = 0;
__device__ unsigned g_bar_gen = 0;

__device__ __forceinline__ void grid_sync() {
    __syncthreads();
    if (threadIdx.x == 0) {
        unsigned gen = *(volatile unsigned*)&g_bar_gen;
        __threadfence();
        unsigned old = atomicAdd(&g_bar_count, 1u);
        if (old == NBLK - 1) {
            *(volatile unsigned*)&g_bar_count = 0u;
            __threadfence();
            atomicAdd(&g_bar_gen, 1u);
        } else {
            while (*(volatile unsigned*)&g_bar_gen == gen) __nanosleep(64);
        }
        __threadfence();
    }
    __syncthreads();
}

__device__ __forceinline__ float sigf(float x) { return 1.0f / (1.0f + expf(-x)); }

// Accumulate acc[g][ib][jj] += A[bi0+b][k] * W[g*512 + j0+j][k] over K.
// A: row-major [*, lda]; W: row-major [2048, ldw].
// smem tiles are stored K-transposed so inner reads are float2-contiguous.
__device__ __forceinline__ void gemm_acc(
    float (&acc)[4][2][2],
    const float* __restrict__ A, int lda,
    const float* __restrict__ W, int ldw,
    int bi0, int j0, int K,
    float (&As)[KC][34], float (&Ws)[4][KC][34])
{
    const int t  = threadIdx.x;
    const int tx = t & 15, ty = t >> 4;
    // A-tile loader mapping: 32 rows x 32 k, one float4 per thread
    const int ab = t >> 3, akq = (t & 7) << 2;
    // W-tile loader mapping: 128 rows (4g x 32j) x 32 k, 4 float4 per thread
    const int wr = t >> 1, wkh = (t & 1) << 4;
    const int wg = wr >> 5, wj = wr & 31;

    const float* Ap = A + (size_t)(bi0 + ab) * lda + akq;
    const float* Wp = W + (size_t)(wg * H_ + j0 + wj) * ldw + wkh;

    // register prefetch of first chunk
    float4 ra  = *(const float4*)(Ap);
    float4 rw0 = *(const float4*)(Wp + 0);
    float4 rw1 = *(const float4*)(Wp + 4);
    float4 rw2 = *(const float4*)(Wp + 8);
    float4 rw3 = *(const float4*)(Wp + 12);

    for (int k0 = 0; k0 < K; k0 += KC) {
        // stage regs -> smem (transposed)
        As[akq + 0][ab] = ra.x; As[akq + 1][ab] = ra.y;
        As[akq + 2][ab] = ra.z; As[akq + 3][ab] = ra.w;
        Ws[wg][wkh + 0][wj] = rw0.x; Ws[wg][wkh + 1][wj] = rw0.y;
        Ws[wg][wkh + 2][wj] = rw0.z; Ws[wg][wkh + 3][wj] = rw0.w;
        Ws[wg][wkh + 4][wj] = rw1.x; Ws[wg][wkh + 5][wj] = rw1.y;
        Ws[wg][wkh + 6][wj] = rw1.z; Ws[wg][wkh + 7][wj] = rw1.w;
        Ws[wg][wkh + 8][wj] = rw2.x; Ws[wg][wkh + 9][wj] = rw2.y;
        Ws[wg][wkh + 10][wj] = rw2.z; Ws[wg][wkh + 11][wj] = rw2.w;
        Ws[wg][wkh + 12][wj] = rw3.x; Ws[wg][wkh + 13][wj] = rw3.y;
        Ws[wg][wkh + 14][wj] = rw3.z; Ws[wg][wkh + 15][wj] = rw3.w;
        __syncthreads();

        // prefetch next chunk while computing this one
        if (k0 + KC < K) {
            ra  = *(const float4*)(Ap + k0 + KC);
            rw0 = *(const float4*)(Wp + k0 + KC + 0);
            rw1 = *(const float4*)(Wp + k0 + KC + 4);
            rw2 = *(const float4*)(Wp + k0 + KC + 8);
            rw3 = *(const float4*)(Wp + k0 + KC + 12);
        }

        #pragma unroll
        for (int kk = 0; kk < KC; kk++) {
            float2 a = *(const float2*)(&As[kk][ty * 2]);
            #pragma unroll
            for (int g = 0; g < 4; g++) {
                float2 w = *(const float2*)(&Ws[g][kk][tx * 2]);
                acc[g][0][0] += a.x * w.x;
                acc[g][0][1] += a.x * w.y;
                acc[g][1][0] += a.y * w.x;
                acc[g][1][1] += a.y * w.y;
            }
        }
        __syncthreads();
    }
}

extern "C" __global__ void __launch_bounds__(NTHR, 1)
lstm_persistent(
    const float* __restrict__ x,     const float* __restrict__ h0,
    const float* __restrict__ c0,    const float* __restrict__ done,
    const float* __restrict__ Wih0,  const float* __restrict__ Whh0,
    const float* __restrict__ bih0,  const float* __restrict__ bhh0,
    const float* __restrict__ Wih1,  const float* __restrict__ Whh1,
    const float* __restrict__ bih1,  const float* __restrict__ bhh1,
    float* __restrict__ out)
{
    __shared__ float As[KC][34];
    __shared__ float Ws[4][KC][34];

    const int t  = threadIdx.x;
    const int tx = t & 15, ty = t >> 4;
    const int bi0 = (blockIdx.x >> 4) * 32;  // batch tile (8 tiles)
    const int j0  = (blockIdx.x & 15) * 32;  // hidden tile (16 tiles)

    // ---- init recurrent state from h0/c0 ----
    for (int i = blockIdx.x * NTHR + t; i < B_ * H_; i += NBLK * NTHR) {
        g_H0buf[0][i] = h0[i];
        g_H1buf[0][i] = h0[B_ * H_ + i];
        g_C0[i] = c0[i];
        g_C1[i] = c0[B_ * H_ + i];
    }

    // preload bias sums (b_ih + b_hh) for this CTA's hidden columns
    float bs0[4][2], bs1[4][2];
    #pragma unroll
    for (int g = 0; g < 4; g++) {
        #pragma unroll
        for (int jj = 0; jj < 2; jj++) {
            int r = g * H_ + j0 + tx * 2 + jj;
            bs0[g][jj] = bih0[r] + bhh0[r];
            bs1[g][jj] = bih1[r] + bhh1[r];
        }
    }

    grid_sync();

    for (int s = 0; s < S_; s++) {
        const int p = s & 1;

        // ================= layer 0 =================
        float acc[4][2][2];
        #pragma unroll
        for (int g = 0; g < 4; g++)
            #pragma unroll
            for (int ib = 0; ib < 2; ib++)
                #pragma unroll
                for (int jj = 0; jj < 2; jj++)
                    acc[g][ib][jj] = bs0[g][jj];

        gemm_acc(acc, x + (size_t)s * B_ * I_, I_, Wih0, I_, bi0, j0, I_, As, Ws);
        gemm_acc(acc, g_H0buf[p],              H_, Whh0, H_, bi0, j0, H_, As, Ws);

        #pragma unroll
        for (int ib = 0; ib < 2; ib++) {
            int b = bi0 + ty * 2 + ib;
            float m = 1.0f - done[s * B_ + b];
            #pragma unroll
            for (int jj = 0; jj < 2; jj++) {
                int j = j0 + tx * 2 + jj;
                int idx = b * H_ + j;
                float ig = sigf(acc[0][ib][jj]);
                float fg = sigf(acc[1][ib][jj]);
                float gg = tanhf(acc[2][ib][jj]);
                float og = sigf(acc[3][ib][jj]);
                float c  = fg * g_C0[idx] + ig * gg;
                float h  = og * tanhf(c);
                g_H0new[p][idx]      = h;       // unmasked -> layer1 input
                g_H0buf[p ^ 1][idx]  = h * m;   // masked   -> next step
                g_C0[idx]            = c * m;
            }
        }

        grid_sync();  // layer1 (all CTAs) needs full g_H0new

        // ================= layer 1 =================
        #pragma unroll
        for (int g = 0; g < 4; g++)
            #pragma unroll
            for (int ib = 0; ib < 2; ib++)
                #pragma unroll
                for (int jj = 0; jj < 2; jj++)
                    acc[g][ib][jj] = bs1[g][jj];

        gemm_acc(acc, g_H0new[p], H_, Wih1, H_, bi0, j0, H_, As, Ws);
        gemm_acc(acc, g_H1buf[p], H_, Whh1, H_, bi0, j0, H_, As, Ws);

        #pragma unroll
        for (int ib = 0; ib < 2; ib++) {
            int b = bi0 + ty * 2 + ib;
            float m = 1.0f - done[s * B_ + b];
            #pragma unroll
            for (int jj = 0; jj < 2; jj++) {
                int j = j0 + tx * 2 + jj;
                int idx = b * H_ + j;
                float ig = sigf(acc[0][ib][jj]);
                float fg = sigf(acc[1][ib][jj]);
                float gg = tanhf(acc[2][ib][jj]);
                float og = sigf(acc[3][ib][jj]);
                float c  = fg * g_C1[idx] + ig * gg;
                float h  = og * tanhf(c);
                out[(size_t)(s * B_ + b) * H_ + j] = h;   // unmasked top output
                g_H1buf[p ^ 1][idx] = h * m;
                g_C1[idx]           = c * m;
            }
        }
        // no end-of-step sync needed: parity double-buffering + the mid-step
        // barrier order every cross-CTA producer/consumer pair (verified).
    }

    grid_sync();

    // ---- final h (L,B,H) then c (L,B,H); S even -> final state in buf[0] ----
    const size_t OHC = (size_t)S_ * B_ * H_;
    for (int i = blockIdx.x * NTHR + t; i < B_ * H_; i += NBLK * NTHR) {
        out[OHC + i]               = g_H0buf[0][i];
        out[OHC + B_ * H_ + i]     = g_H1buf[0][i];
        out[OHC + 2 * B_ * H_ + i] = g_C0[i];
        out[OHC + 3 * B_ * H_ + i] = g_C1[i];
    }
}

extern "C" void kernel_launch(void* const* d_in, const int* in_sizes, int n_in,
                              void* d_out, int out_size) {
    (void)in_sizes; (void)n_in; (void)out_size;
    lstm_persistent<<<NBLK, NTHR>>>(
        (const float*)d_in[0],  (const float*)d_in[1],
        (const float*)d_in[2],  (const float*)d_in[3],
        (const float*)d_in[4],  (const float*)d_in[5],
        (const float*)d_in[6],  (const float*)d_in[7],
        (const float*)d_in[8],  (const float*)d_in[9],
        (const float*)d_in[10], (const float*)d_in[11],
        (float*)d_out);
}

// round 3
// speedup vs baseline: 1.0012x; 1.0012x over previous
#include <cuda_runtime.h>
#include <math.h>

// LSTMBackbone: 2-layer LSTM, S=256, B=256, I=256, H=512, done-mask reset.
// Persistent single-kernel design: 128 CTAs, custom grid barrier, 1 sync/step.
// Each CTA computes a 32x32 (batch x hidden) tile of cells, all 4 gates.

#define S_ 256
#define B_ 256
#define I_ 256
#define H_ 512
#define NBLK 128
#define NTHR 256
#define KC 32

// ---- persistent device state (allocation-free scratch) ----
__device__ float g_H0buf[2][B_ * H_];   // layer0 h, masked, parity ping-pong
__device__ float g_H1buf[2][B_ * H_];   // layer1 h, masked, parity ping-pong
__device__ float g_H0new[2][B_ * H_];   // layer0 h unmasked (feeds layer1), parity
__device__ float g_C0[B_ * H_];         // cell states (owner-thread access only)
__device__ float g_C1[B_ * H_];
__device__ unsigned g_bar_count = 0;
__device__ unsigned g_bar_gen = 0;

__device__ __forceinline__ void grid_sync() {
    __syncthreads();
    if (threadIdx.x == 0) {
        unsigned gen = *(volatile unsigned*)&g_bar_gen;
        __threadfence();
        unsigned old = atomicAdd(&g_bar_count, 1u);
        if (old == NBLK - 1) {
            *(volatile unsigned*)&g_bar_count = 0u;
            __threadfence();
            atomicAdd(&g_bar_gen, 1u);
        } else {
            while (*(volatile unsigned*)&g_bar_gen == gen) __nanosleep(64);
        }
        __threadfence();
    }
    __syncthreads();
}

__device__ __forceinline__ float sigf(float x) { return 1.0f / (1.0f + expf(-x)); }

// Accumulate acc[g][ib][jj] += A[bi0+b][k] * W[g*512 + j0+j][k] over K.
// A: row-major [*, lda]; W: row-major [2048, ldw].
// smem tiles are stored K-transposed so inner reads are float2-contiguous.
__device__ __forceinline__ void gemm_acc(
    float (&acc)[4][2][2],
    const float* __restrict__ A, int lda,
    const float* __restrict__ W, int ldw,
    int bi0, int j0, int K,
    float (&As)[KC][34], float (&Ws)[4][KC][34])
{
    const int t  = threadIdx.x;
    const int tx = t & 15, ty = t >> 4;
    // A-tile loader mapping: 32 rows x 32 k, one float4 per thread
    const int ab = t >> 3, akq = (t & 7) << 2;
    // W-tile loader mapping: 128 rows (4g x 32j) x 32 k, 4 float4 per thread
    const int wr = t >> 1, wkh = (t & 1) << 4;
    const int wg = wr >> 5, wj = wr & 31;

    const float* Ap = A + (size_t)(bi0 + ab) * lda + akq;
    const float* Wp = W + (size_t)(wg * H_ + j0 + wj) * ldw + wkh;

    // register prefetch of first chunk
    float4 ra  = *(const float4*)(Ap);
    float4 rw0 = *(const float4*)(Wp + 0);
    float4 rw1 = *(const float4*)(Wp + 4);
    float4 rw2 = *(const float4*)(Wp + 8);
    float4 rw3 = *(const float4*)(Wp + 12);

    for (int k0 = 0; k0 < K; k0 += KC) {
        // stage regs -> smem (transposed)
        As[akq + 0][ab] = ra.x; As[akq + 1][ab] = ra.y;
        As[akq + 2][ab] = ra.z; As[akq + 3][ab] = ra.w;
        Ws[wg][wkh + 0][wj] = rw0.x; Ws[wg][wkh + 1][wj] = rw0.y;
        Ws[wg][wkh + 2][wj] = rw0.z; Ws[wg][wkh + 3][wj] = rw0.w;
        Ws[wg][wkh + 4][wj] = rw1.x; Ws[wg][wkh + 5][wj] = rw1.y;
        Ws[wg][wkh + 6][wj] = rw1.z; Ws[wg][wkh + 7][wj] = rw1.w;
        Ws[wg][wkh + 8][wj] = rw2.x; Ws[wg][wkh + 9][wj] = rw2.y;
        Ws[wg][wkh + 10][wj] = rw2.z; Ws[wg][wkh + 11][wj] = rw2.w;
        Ws[wg][wkh + 12][wj] = rw3.x; Ws[wg][wkh + 13][wj] = rw3.y;
        Ws[wg][wkh + 14][wj] = rw3.z; Ws[wg][wkh + 15][wj] = rw3.w;
        __syncthreads();

        // prefetch next chunk while computing this one
        if (k0 + KC < K) {
            ra  = *(const float4*)(Ap + k0 + KC);
            rw0 = *(const float4*)(Wp + k0 + KC + 0);
            rw1 = *(const float4*)(Wp + k0 + KC + 4);
            rw2 = *(const float4*)(Wp + k0 + KC + 8);
            rw3 = *(const float4*)(Wp + k0 + KC + 12);
        }

        #pragma unroll
        for (int kk = 0; kk < KC; kk++) {
            float2 a = *(const float2*)(&As[kk][ty * 2]);
            #pragma unroll
            for (int g = 0; g < 4; g++) {
                float2 w = *(const float2*)(&Ws[g][kk][tx * 2]);
                acc[g][0][0] += a.x * w.x;
                acc[g][0][1] += a.x * w.y;
                acc[g][1][0] += a.y * w.x;
                acc[g][1][1] += a.y * w.y;
            }
        }
        __syncthreads();
    }
}

extern "C" __global__ void __launch_bounds__(NTHR, 1)
lstm_persistent(
    const float* __restrict__ x,     const float* __restrict__ h0,
    const float* __restrict__ c0,    const float* __restrict__ done,
    const float* __restrict__ Wih0,  const float* __restrict__ Whh0,
    const float* __restrict__ bih0,  const float* __restrict__ bhh0,
    const float* __restrict__ Wih1,  const float* __restrict__ Whh1,
    const float* __restrict__ bih1,  const float* __restrict__ bhh1,
    float* __restrict__ out)
{
    __shared__ float As[KC][34];
    __shared__ float Ws[4][KC][34];

    const int t  = threadIdx.x;
    const int tx = t & 15, ty = t >> 4;
    const int bi0 = (blockIdx.x >> 4) * 32;  // batch tile (8 tiles)
    const int j0  = (blockIdx.x & 15) * 32;  // hidden tile (16 tiles)

    // ---- init recurrent state from h0/c0 ----
    for (int i = blockIdx.x * NTHR + t; i < B_ * H_; i += NBLK * NTHR) {
        g_H0buf[0][i] = h0[i];
        g_H1buf[0][i] = h0[B_ * H_ + i];
        g_C0[i] = c0[i];
        g_C1[i] = c0[B_ * H_ + i];
    }

    // preload bias sums (b_ih + b_hh) for this CTA's hidden columns
    float bs0[4][2], bs1[4][2];
    #pragma unroll
    for (int g = 0; g < 4; g++) {
        #pragma unroll
        for (int jj = 0; jj < 2; jj++) {
            int r = g * H_ + j0 + tx * 2 + jj;
            bs0[g][jj] = bih0[r] + bhh0[r];
            bs1[g][jj] = bih1[r] + bhh1[r];
        }
    }

    grid_sync();

    for (int s = 0; s < S_; s++) {
        const int p = s & 1;

        // ================= layer 0 =================
        float acc[4][2][2];
        #pragma unroll
        for (int g = 0; g < 4; g++)
            #pragma unroll
            for (int ib = 0; ib < 2; ib++)
                #pragma unroll
                for (int jj = 0; jj < 2; jj++)
                    acc[g][ib][jj] = bs0[g][jj];

        gemm_acc(acc, x + (size_t)s * B_ * I_, I_, Wih0, I_, bi0, j0, I_, As, Ws);
        gemm_acc(acc, g_H0buf[p],              H_, Whh0, H_, bi0, j0, H_, As, Ws);

        #pragma unroll
        for (int ib = 0; ib < 2; ib++) {
            int b = bi0 + ty * 2 + ib;
            float m = 1.0f - done[s * B_ + b];
            #pragma unroll
            for (int jj = 0; jj < 2; jj++) {
                int j = j0 + tx * 2 + jj;
                int idx = b * H_ + j;
                float ig = sigf(acc[0][ib][jj]);
                float fg = sigf(acc[1][ib][jj]);
                float gg = tanhf(acc[2][ib][jj]);
                float og = sigf(acc[3][ib][jj]);
                float c  = fg * g_C0[idx] + ig * gg;
                float h  = og * tanhf(c);
                g_H0new[p][idx]      = h;       // unmasked -> layer1 input
                g_H0buf[p ^ 1][idx]  = h * m;   // masked   -> next step
                g_C0[idx]            = c * m;
            }
        }

        grid_sync();  // layer1 (all CTAs) needs full g_H0new

        // ================= layer 1 =================
        #pragma unroll
        for (int g = 0; g < 4; g++)
            #pragma unroll
            for (int ib = 0; ib < 2; ib++)
                #pragma unroll
                for (int jj = 0; jj < 2; jj++)
                    acc[g][ib][jj] = bs1[g][jj];

        gemm_acc(acc, g_H0new[p], H_, Wih1, H_, bi0, j0, H_, As, Ws);
        gemm_acc(acc, g_H1buf[p], H_, Whh1, H_, bi0, j0, H_, As, Ws);

        #pragma unroll
        for (int ib = 0; ib < 2; ib++) {
            int b = bi0 + ty * 2 + ib;
            float m = 1.0f - done[s * B_ + b];
            #pragma unroll
            for (int jj = 0; jj < 2; jj++) {
                int j = j0 + tx * 2 + jj;
                int idx = b * H_ + j;
                float ig = sigf(acc[0][ib][jj]);
                float fg = sigf(acc[1][ib][jj]);
                float gg = tanhf(acc[2][ib][jj]);
                float og = sigf(acc[3][ib][jj]);
                float c  = fg * g_C1[idx] + ig * gg;
                float h  = og * tanhf(c);
                out[(size_t)(s * B_ + b) * H_ + j] = h;   // unmasked top output
                g_H1buf[p ^ 1][idx] = h * m;
                g_C1[idx]           = c * m;
            }
        }
        // no end-of-step sync needed: parity double-buffering + the mid-step
        // barrier order every cross-CTA producer/consumer pair (verified).
    }

    grid_sync();

    // ---- final h (L,B,H) then c (L,B,H); S even -> final state in buf[0] ----
    const size_t OHC = (size_t)S_ * B_ * H_;
    for (int i = blockIdx.x * NTHR + t; i < B_ * H_; i += NBLK * NTHR) {
        out[OHC + i]               = g_H0buf[0][i];
        out[OHC + B_ * H_ + i]     = g_H1buf[0][i];
        out[OHC + 2 * B_ * H_ + i] = g_C0[i];
        out[OHC + 3 * B_ * H_ + i] = g_C1[i];
    }
}

extern "C" void kernel_launch(void* const* d_in, const int* in_sizes, int n_in,
                              void* d_out, int out_size) {
    (void)in_sizes; (void)n_in; (void)out_size;
    lstm_persistent<<<NBLK, NTHR>>>(
        (const float*)d_in[0],  (const float*)d_in[1],
        (const float*)d_in[2],  (const float*)d_in[3],
        (const float*)d_in[4],  (const float*)d_in[5],
        (const float*)d_in[6],  (const float*)d_in[7],
        (const float*)d_in[8],  (const float*)d_in[9],
        (const float*)d_in[10], (const float*)d_in[11],
        (float*)d_out);
}